// round 4
// baseline (speedup 1.0000x reference)
#include <cuda_runtime.h>
#include <cuda_bf16.h>
#include <cstdint>

// ScaleLayer: y[b,d] = x[b,d] * exp(diag[d]);  second output = raw diag.
// x: [16384, 4096] fp32 row-major; diag: [4096] fp32.
//
// R4: R1's measured-best memory pattern (4 front-batched LDG.128/thread,
// 256 thr, grid=16384, ~32 regs -> ~82% occ) with the loop removed (exact
// single-pass cover) and evict-first stores (__stcs). exp(diag) precomputed
// once into a __device__ table by a (measured-free) prologue kernel.

#define D_DIM 4096
#define B_DIM 16384

__device__ float g_ediag[D_DIM];

__global__ void prep_kernel(const float* __restrict__ diag,
                            float* __restrict__ out_tail,
                            int write_tail) {
    int i = blockIdx.x * blockDim.x + threadIdx.x;
    if (i < D_DIM) {
        float d = diag[i];
        g_ediag[i] = expf(d);
        if (write_tail) out_tail[i] = d;
    }
}

// total4 = 16,777,216 float4.  grid*block = 4,194,304 threads = total4/4.
// Each thread handles elements {j, j+S, j+2S, j+3S} with S = total threads:
// exact cover, no loop, no tail.
__global__ void __launch_bounds__(256)
scale_kernel(const float4* __restrict__ x, float4* __restrict__ y) {
    constexpr int S = (B_DIM * D_DIM) / 4 / 4;     // 4,194,304 (= grid*block)
    const float4* __restrict__ ed =
        reinterpret_cast<const float4*>(g_ediag);  // 1024 float4 columns

    const int j = blockIdx.x * blockDim.x + threadIdx.x;
    const int j0 = j;
    const int j1 = j + S;
    const int j2 = j + 2 * S;
    const int j3 = j + 3 * S;

    // Front-batched independent loads (MLP=4).
    float4 v0 = x[j0];
    float4 v1 = x[j1];
    float4 v2 = x[j2];
    float4 v3 = x[j3];

    // S is a multiple of D_DIM/4, so all four indices share the same column:
    // one exp-table load serves all four rows.
    float4 e = ed[j0 & (D_DIM / 4 - 1)];

    v0.x *= e.x; v0.y *= e.y; v0.z *= e.z; v0.w *= e.w;
    v1.x *= e.x; v1.y *= e.y; v1.z *= e.z; v1.w *= e.w;
    v2.x *= e.x; v2.y *= e.y; v2.z *= e.z; v2.w *= e.w;
    v3.x *= e.x; v3.y *= e.y; v3.z *= e.z; v3.w *= e.w;

    // Evict-first stores: output is never re-read.
    __stcs(y + j0, v0);
    __stcs(y + j1, v1);
    __stcs(y + j2, v2);
    __stcs(y + j3, v3);
}

extern "C" void kernel_launch(void* const* d_in, const int* in_sizes, int n_in,
                              void* d_out, int out_size) {
    const float* x    = (const float*)d_in[0];
    const float* diag = (const float*)d_in[1];
    float* out = (float*)d_out;

    const long long n_main = (long long)B_DIM * D_DIM;
    const int write_tail = (out_size > n_main) ? 1 : 0;

    prep_kernel<<<(D_DIM + 255) / 256, 256>>>(diag, out + n_main, write_tail);

    // 16,777,216 float4 / (256 thr * 4 per thread) = 16384 CTAs, exact.
    scale_kernel<<<16384, 256>>>((const float4*)x, (float4*)out);
}